// round 10
// baseline (speedup 1.0000x reference)
#include <cuda_runtime.h>
#include <cuda_fp16.h>
#include <math.h>
#include <cstdint>

#define NMAX 100000
#define EMAX 1600000
#define D 64
#define KDIM 192
#define OUTC 64

typedef unsigned long long u64;

// ---- scratch ----
__device__ int    g_cnt[NMAX];          // zero-init; self-cleaned by scan_partial
__device__ int    g_start[NMAX + 1];
__device__ int    g_cursor[NMAX];
__device__ int    g_adj[EMAX];
__device__ int    g_bsum[260];
__device__ uint2  g_feat16[(size_t)NMAX * 16];   // [N, 64] fp16, 4 dims per uint2
__device__ float  g_sum[(size_t)NMAX * D];       // [N, 64] fp32 sum
__device__ __half g_mm[(size_t)NMAX * 2 * D];    // [N, 128] fp16: max(0..63) | min(64..127)

// ---------------- feature fp32 -> fp16 conversion ----------------

__global__ __launch_bounds__(256) void featcvt_kernel(const float* __restrict__ feat, int total4) {
    int i = blockIdx.x * blockDim.x + threadIdx.x;   // over N*D/4
    if (i < total4) {
        float4 v = *(const float4*)&feat[(size_t)i * 4];
        __half2 h0 = __floats2half2_rn(v.x, v.y);
        __half2 h1 = __floats2half2_rn(v.z, v.w);
        uint2 u;
        u.x = *(uint32_t*)&h0;
        u.y = *(uint32_t*)&h1;
        g_feat16[i] = u;
    }
}

// ---------------- CSR build ----------------

__global__ void hist_kernel(const int* __restrict__ row, int E) {
    int i = blockIdx.x * blockDim.x + threadIdx.x;
    if (i < E) atomicAdd(&g_cnt[row[i]], 1);
}

#define SCAN_B 512

__global__ __launch_bounds__(SCAN_B) void scan_partial_kernel(int n) {
    __shared__ int ws[16];
    int blk = blockIdx.x, tid = threadIdx.x;
    int i = blk * SCAN_B + tid;
    int v = (i < n) ? g_cnt[i] : 0;
    if (i < n) g_cnt[i] = 0;                   // self-clean for next call
    int lane = tid & 31, wid = tid >> 5;
    int x = v;
    #pragma unroll
    for (int o = 1; o < 32; o <<= 1) {
        int y = __shfl_up_sync(0xffffffffu, x, o);
        if (lane >= o) x += y;
    }
    if (lane == 31) ws[wid] = x;
    __syncthreads();
    if (wid == 0 && lane < 16) {
        int w = ws[lane];
        #pragma unroll
        for (int o = 1; o < 16; o <<= 1) {
            int y = __shfl_up_sync(0x0000ffffu, w, o);
            if (lane >= o) w += y;
        }
        ws[lane] = w;
    }
    __syncthreads();
    int incl = x + (wid > 0 ? ws[wid - 1] : 0);
    if (i < n) g_start[i] = incl - v;          // block-local exclusive
    if (tid == SCAN_B - 1) g_bsum[blk] = incl; // block total
}

// scan_add with inlined block-offset reduction over g_bsum[0..bid)
__global__ __launch_bounds__(SCAN_B) void scan_add_kernel(int n, int nb) {
    __shared__ int ws[16];
    int bid = blockIdx.x, tid = threadIdx.x;
    int lane = tid & 31, wid = tid >> 5;

    int v = (tid < bid) ? g_bsum[tid] : 0;
    #pragma unroll
    for (int o = 16; o > 0; o >>= 1) v += __shfl_down_sync(0xffffffffu, v, o);
    if (lane == 0) ws[wid] = v;
    __syncthreads();
    if (wid == 0) {
        int w = (lane < 16) ? ws[lane] : 0;
        #pragma unroll
        for (int o = 8; o > 0; o >>= 1) w += __shfl_down_sync(0xffffffffu, w, o);
        if (lane == 0) ws[0] = w;
    }
    __syncthreads();
    int off = ws[0];

    int i = bid * SCAN_B + tid;
    if (i < n) {
        int s = g_start[i] + off;
        g_start[i] = s;
        g_cursor[i] = s;
    }
    if (tid == 0 && bid == nb - 1) g_start[n] = off + g_bsum[bid];
}

__global__ void scatter_kernel(const int* __restrict__ row,
                               const int* __restrict__ col, int E) {
    int i = blockIdx.x * blockDim.x + threadIdx.x;
    if (i < E) {
        int p = atomicAdd(&g_cursor[row[i]], 1);
        g_adj[p] = col[i];
    }
}

// ---------------- aggregation: half-warp per node, fp16 gathers ----------------
// sum accumulated fp32 -> g_sum; max/min kept in half2 (exact) -> g_mm.

__device__ __forceinline__ void acc16(float4& sm, __half2& mxa, __half2& mxb,
                                      __half2& mna, __half2& mnb, uint2 u) {
    __half2 h0 = *(__half2*)&u.x;
    __half2 h1 = *(__half2*)&u.y;
    mxa = __hmax2(mxa, h0);  mxb = __hmax2(mxb, h1);
    mna = __hmin2(mna, h0);  mnb = __hmin2(mnb, h1);
    float2 f0 = __half22float2(h0);
    float2 f1 = __half22float2(h1);
    sm.x += f0.x;  sm.y += f0.y;  sm.z += f1.x;  sm.w += f1.y;
}

__global__ __launch_bounds__(256) void aggregate_kernel(int n) {
    int gt   = blockIdx.x * blockDim.x + threadIdx.x;
    int node = gt >> 4;
    int lane = gt & 15;
    if (node >= n) return;

    int s = g_start[node];
    int e = g_start[node + 1];

    float4 sm = make_float4(0.f, 0.f, 0.f, 0.f);
    __half2 ninf2 = __float2half2_rn(-INFINITY);
    __half2 pinf2 = __float2half2_rn( INFINITY);
    __half2 mxa = ninf2, mxb = ninf2;
    __half2 mna = pinf2, mnb = pinf2;

    int j = s;
    for (; j + 4 <= e; j += 4) {
        int c0 = __ldg(&g_adj[j]);
        int c1 = __ldg(&g_adj[j + 1]);
        int c2 = __ldg(&g_adj[j + 2]);
        int c3 = __ldg(&g_adj[j + 3]);
        uint2 u0 = g_feat16[(size_t)c0 * 16 + lane];
        uint2 u1 = g_feat16[(size_t)c1 * 16 + lane];
        uint2 u2 = g_feat16[(size_t)c2 * 16 + lane];
        uint2 u3 = g_feat16[(size_t)c3 * 16 + lane];
        acc16(sm, mxa, mxb, mna, mnb, u0);
        acc16(sm, mxa, mxb, mna, mnb, u1);
        acc16(sm, mxa, mxb, mna, mnb, u2);
        acc16(sm, mxa, mxb, mna, mnb, u3);
    }
    for (; j < e; j++) {
        int c0 = __ldg(&g_adj[j]);
        uint2 u0 = g_feat16[(size_t)c0 * 16 + lane];
        acc16(sm, mxa, mxb, mna, mnb, u0);
    }

    if (e == s) {
        __half2 z = __float2half2_rn(0.f);
        mxa = z; mxb = z; mna = z; mnb = z;
    }

    *(float4*)&g_sum[(size_t)node * D + 4 * lane] = sm;
    uint2 mxw, mnw;
    mxw.x = *(uint32_t*)&mxa;  mxw.y = *(uint32_t*)&mxb;
    mnw.x = *(uint32_t*)&mna;  mnw.y = *(uint32_t*)&mnb;
    __half* mm = &g_mm[(size_t)node * 2 * D];
    *(uint2*)&mm[      4 * lane] = mxw;
    *(uint2*)&mm[D  +  4 * lane] = mnw;
}

// ---------------- MLP GEMM with packed f32x2 FMA, mixed-precision A ----------------
// K-tiles 0..3 (k<64) read fp32 g_sum; tiles 4..11 read fp16 g_mm (exact convert).

__device__ __forceinline__ u64 pack2(float lo, float hi) {
    u64 r; asm("mov.b64 %0, {%1, %2};" : "=l"(r) : "f"(lo), "f"(hi)); return r;
}
__device__ __forceinline__ void ffma2(u64& d, u64 a, u64 b) {
    asm("fma.rn.f32x2 %0, %1, %2, %0;" : "+l"(d) : "l"(a), "l"(b));
}
__device__ __forceinline__ float2 unpack2(u64 v) {
    float2 f; asm("mov.b64 {%0, %1}, %2;" : "=f"(f.x), "=f"(f.y) : "l"(v)); return f;
}

#define BM 128
#define BK 16
#define BN 64

__global__ __launch_bounds__(256) void mlp_gemm_kernel(
    const float* __restrict__ Wg,     // [192,64]
    const float* __restrict__ bg,     // [64]
    float* __restrict__ out, int n)
{
    __shared__ float As[BK][BM];
    __shared__ float Bs[BK][BN];

    int tid = threadIdx.x;
    int block_m = blockIdx.x * BM;
    int tx = tid & 15;
    int ty = tid >> 4;

    int a_row  = tid >> 2;
    int a_col4 = (tid & 3) * 4;
    int b_row  = tid >> 4;
    int b_col4 = (tid & 15) * 4;

    u64 acc[4][4];
    #pragma unroll
    for (int i = 0; i < 4; i++)
        #pragma unroll
        for (int j = 0; j < 4; j++) acc[i][j] = 0ull;

    for (int k0 = 0; k0 < KDIM; k0 += BK) {
        #pragma unroll
        for (int r = 0; r < 2; r++) {
            int m  = a_row + r * 64;
            int gm = block_m + m;
            float4 v = make_float4(0.f, 0.f, 0.f, 0.f);
            if (gm < n) {
                if (k0 < D) {
                    v = *(const float4*)&g_sum[(size_t)gm * D + k0 + a_col4];
                } else {
                    uint2 u = *(const uint2*)&g_mm[(size_t)gm * 2 * D + (k0 - D) + a_col4];
                    __half2 h0 = *(__half2*)&u.x;
                    __half2 h1 = *(__half2*)&u.y;
                    float2 f0 = __half22float2(h0);
                    float2 f1 = __half22float2(h1);
                    v = make_float4(f0.x, f0.y, f1.x, f1.y);
                }
            }
            As[a_col4 + 0][m] = v.x;
            As[a_col4 + 1][m] = v.y;
            As[a_col4 + 2][m] = v.z;
            As[a_col4 + 3][m] = v.w;
        }
        *(float4*)&Bs[b_row][b_col4] =
            *(const float4*)&Wg[(size_t)(k0 + b_row) * BN + b_col4];
        __syncthreads();

        #pragma unroll
        for (int k = 0; k < BK; k++) {
            u64 ra[4];
            #pragma unroll
            for (int i = 0; i < 4; i++)
                ra[i] = *(const u64*)&As[k][ty * 8 + 2 * i];
            float4 rbv = *(const float4*)&Bs[k][tx * 4];
            u64 rb[4];
            rb[0] = pack2(rbv.x, rbv.x);
            rb[1] = pack2(rbv.y, rbv.y);
            rb[2] = pack2(rbv.z, rbv.z);
            rb[3] = pack2(rbv.w, rbv.w);
            #pragma unroll
            for (int i = 0; i < 4; i++)
                #pragma unroll
                for (int j = 0; j < 4; j++)
                    ffma2(acc[i][j], ra[i], rb[j]);
        }
        __syncthreads();
    }

    float4 bv = *(const float4*)&bg[tx * 4];
    #pragma unroll
    for (int i = 0; i < 4; i++) {
        float2 c0 = unpack2(acc[i][0]);
        float2 c1 = unpack2(acc[i][1]);
        float2 c2 = unpack2(acc[i][2]);
        float2 c3 = unpack2(acc[i][3]);
        int gm0 = block_m + ty * 8 + 2 * i;
        if (gm0 < n) {
            float4 o;
            o.x = tanhf(c0.x + bv.x); o.y = tanhf(c1.x + bv.y);
            o.z = tanhf(c2.x + bv.z); o.w = tanhf(c3.x + bv.w);
            *(float4*)&out[(size_t)gm0 * OUTC + tx * 4] = o;
        }
        if (gm0 + 1 < n) {
            float4 o;
            o.x = tanhf(c0.y + bv.x); o.y = tanhf(c1.y + bv.y);
            o.z = tanhf(c2.y + bv.z); o.w = tanhf(c3.y + bv.w);
            *(float4*)&out[(size_t)(gm0 + 1) * OUTC + tx * 4] = o;
        }
    }
}

// ---------------- launch ----------------

extern "C" void kernel_launch(void* const* d_in, const int* in_sizes, int n_in,
                              void* d_out, int out_size) {
    const int*   row  = (const int*)d_in[0];
    const int*   col  = (const int*)d_in[1];
    const float* feat = (const float*)d_in[2];
    const float* W    = (const float*)d_in[3];
    const float* b    = (const float*)d_in[4];
    float* out = (float*)d_out;

    int E = in_sizes[0];
    int N = in_sizes[2] / D;
    int nb = (N + SCAN_B - 1) / SCAN_B;
    int total4 = N * D / 4;

    featcvt_kernel<<<(total4 + 255) / 256, 256>>>(feat, total4);
    hist_kernel<<<(E + 255) / 256, 256>>>(row, E);
    scan_partial_kernel<<<nb, SCAN_B>>>(N);
    scan_add_kernel<<<nb, SCAN_B>>>(N, nb);
    scatter_kernel<<<(E + 255) / 256, 256>>>(row, col, E);
    aggregate_kernel<<<(N * 16 + 255) / 256, 256>>>(N);
    mlp_gemm_kernel<<<(N + BM - 1) / BM, 256>>>(W, b, out, N);
}